// round 15
// baseline (speedup 1.0000x reference)
#include <cuda_runtime.h>
#include <cuda_bf16.h>
#include <cstdint>

// ---------------------------------------------------------------------------
// ACCGraphSAGE: h0 = relu(feat@W0); 3x { agg = mean_in(h); h = relu(agg@Ws[l]) }
// out = concat([h0..h3], dim=1) -> [N, 512] fp32
// R15: GEMM retiled to 64x64 outputs (N split across 2 CTAs); smem 64KB ->
//      3 CTAs/SM (24 warps). W pre-swizzled into 64-col halves (128B pitch).
//      Rest = R14 (prep, PDL chain, agg at LTS floor).
// ---------------------------------------------------------------------------

#define MAX_N 50000
#define MAX_E 800000
#define HID 128
#define NTILES ((MAX_N + 63) / 64)
#define DEG_CAP 128

__device__ int g_counts[MAX_N];
__device__ int g_csr_src[MAX_N * DEG_CAP];
__device__ __align__(16) unsigned char g_xh[NTILES * 16384];
__device__ __align__(16) unsigned char g_xl[NTILES * 16384];
// W: 4 layers x 2 halves x (128 k x 64 n) bf16, 128B-pitch swizzled (16KB each)
__device__ __align__(16) unsigned char g_wh[4 * 32768];
__device__ __align__(16) unsigned char g_wl[4 * 32768];

// ---------------------------------------------------------------------------
// helpers
// ---------------------------------------------------------------------------
#define GDC_WAIT()    asm volatile("griddepcontrol.wait;" ::: "memory")
#define GDC_TRIGGER() asm volatile("griddepcontrol.launch_dependents;" ::: "memory")
#define CP_COMMIT()   asm volatile("cp.async.commit_group;" ::: "memory")
#define CP_WAIT0()    asm volatile("cp.async.wait_group 0;" ::: "memory")

__device__ __forceinline__ void cp16(uint32_t saddr, const void* gaddr) {
    asm volatile("cp.async.cg.shared.global [%0], [%1], 16;"
                 :: "r"(saddr), "l"(gaddr) : "memory");
}

__device__ __forceinline__ uint32_t s2u(const void* p) {
    uint32_t a;
    asm("{ .reg .u64 t; cvta.to.shared.u64 t, %1; cvt.u32.u64 %0, t; }"
        : "=r"(a) : "l"(p));
    return a;
}

// 256B-pitch swizzle (X tiles: 64 rows x 128 bf16)
__device__ __forceinline__ uint32_t swz(uint32_t row, uint32_t kelem) {
    return row * 256u + ((((kelem >> 3) ^ (row & 7u)) & 15u) << 4) +
           ((kelem & 7u) << 1);
}
// 128B-pitch swizzle (W half tiles: 128 k-rows x 64 bf16)
__device__ __forceinline__ uint32_t swz64(uint32_t row, uint32_t kelem) {
    return row * 128u + ((((kelem >> 3) ^ (row & 7u)) & 7u) << 4) +
           ((kelem & 7u) << 1);
}

__device__ __forceinline__ void ldsm_x4(uint32_t* d, uint32_t addr) {
    asm volatile("ldmatrix.sync.aligned.m8n8.x4.shared.b16 {%0,%1,%2,%3}, [%4];"
                 : "=r"(d[0]), "=r"(d[1]), "=r"(d[2]), "=r"(d[3]) : "r"(addr));
}
__device__ __forceinline__ void ldsm_x4t(uint32_t* d, uint32_t addr) {
    asm volatile("ldmatrix.sync.aligned.m8n8.x4.trans.shared.b16 {%0,%1,%2,%3}, [%4];"
                 : "=r"(d[0]), "=r"(d[1]), "=r"(d[2]), "=r"(d[3]) : "r"(addr));
}
__device__ __forceinline__ void mma_bf16(float* c, const uint32_t* a,
                                         const uint32_t* b) {
    asm volatile(
        "mma.sync.aligned.m16n8k16.row.col.f32.bf16.bf16.f32 "
        "{%0,%1,%2,%3}, {%4,%5,%6,%7}, {%8,%9}, {%0,%1,%2,%3};"
        : "+f"(c[0]), "+f"(c[1]), "+f"(c[2]), "+f"(c[3])
        : "r"(a[0]), "r"(a[1]), "r"(a[2]), "r"(a[3]), "r"(b[0]), "r"(b[1]));
}

__device__ __forceinline__ void add2(unsigned long long& d, unsigned long long v) {
    asm("add.rn.f32x2 %0, %0, %1;" : "+l"(d) : "l"(v));
}
__device__ __forceinline__ float2 unpack2(unsigned long long v) {
    float2 f;
    asm("mov.b64 {%0, %1}, %2;" : "=f"(f.x), "=f"(f.y) : "l"(v));
    return f;
}

// split fp32 quad -> hi/lo bf16 pairs
__device__ __forceinline__ void split4(float4 v, __nv_bfloat162& h01,
                                       __nv_bfloat162& h23,
                                       __nv_bfloat162& l01,
                                       __nv_bfloat162& l23) {
    h01 = __floats2bfloat162_rn(v.x, v.y);
    h23 = __floats2bfloat162_rn(v.z, v.w);
    l01 = __floats2bfloat162_rn(v.x - __bfloat162float(h01.x),
                                v.y - __bfloat162float(h01.y));
    l23 = __floats2bfloat162_rn(v.z - __bfloat162float(h23.x),
                                v.w - __bfloat162float(h23.y));
}

// X-tile store (256B pitch)
__device__ __forceinline__ void store_hilo(unsigned char* xh, unsigned char* xl,
                                           size_t tileBase, uint32_t r, uint32_t k,
                                           float4 v) {
    __nv_bfloat162 h01, h23, l01, l23;
    split4(v, h01, h23, l01, l23);
    uint32_t o0 = swz(r, k), o1 = swz(r, k + 2);
    *reinterpret_cast<__nv_bfloat162*>(xh + tileBase + o0) = h01;
    *reinterpret_cast<__nv_bfloat162*>(xh + tileBase + o1) = h23;
    *reinterpret_cast<__nv_bfloat162*>(xl + tileBase + o0) = l01;
    *reinterpret_cast<__nv_bfloat162*>(xl + tileBase + o1) = l23;
}

// W-half store (128B pitch)
__device__ __forceinline__ void store_hilo64(unsigned char* wh, unsigned char* wl,
                                             size_t base, uint32_t k, uint32_t n,
                                             float4 v) {
    __nv_bfloat162 h01, h23, l01, l23;
    split4(v, h01, h23, l01, l23);
    uint32_t o0 = swz64(k, n), o1 = swz64(k, n + 2);
    *reinterpret_cast<__nv_bfloat162*>(wh + base + o0) = h01;
    *reinterpret_cast<__nv_bfloat162*>(wh + base + o1) = h23;
    *reinterpret_cast<__nv_bfloat162*>(wl + base + o0) = l01;
    *reinterpret_cast<__nv_bfloat162*>(wl + base + o1) = l23;
}

// ---------------------------------------------------------------------------
// prep: scatter (bucketed CSR) + weight/feat conversion in ONE kernel.
// W layout: [layer][half][k=128][n=64], 16KB per (layer,half,hi/lo).
// ---------------------------------------------------------------------------
__global__ void prep_kernel(const int* __restrict__ src, const int* __restrict__ dst,
                            int* __restrict__ cursor, int* __restrict__ csr, int E,
                            const float* __restrict__ feat,
                            const float* __restrict__ W0,
                            const float* __restrict__ Ws,
                            unsigned char* __restrict__ xh,
                            unsigned char* __restrict__ xl,
                            unsigned char* __restrict__ wh,
                            unsigned char* __restrict__ wl,
                            int L, int N, int scatterBlks) {
    if ((int)blockIdx.x < scatterBlks) {
        int i = (blockIdx.x * blockDim.x + threadIdx.x) * 4;
        if (i + 4 <= E) {
            int4 d = *reinterpret_cast<const int4*>(dst + i);
            int4 s = *reinterpret_cast<const int4*>(src + i);
            int p0 = atomicAdd(&cursor[d.x], 1);
            int p1 = atomicAdd(&cursor[d.y], 1);
            int p2 = atomicAdd(&cursor[d.z], 1);
            int p3 = atomicAdd(&cursor[d.w], 1);
            if (p0 < DEG_CAP) csr[d.x * DEG_CAP + p0] = s.x;
            if (p1 < DEG_CAP) csr[d.y * DEG_CAP + p1] = s.y;
            if (p2 < DEG_CAP) csr[d.z * DEG_CAP + p2] = s.z;
            if (p3 < DEG_CAP) csr[d.w * DEG_CAP + p3] = s.w;
        } else {
            for (; i < E; i++) {
                int d = dst[i];
                int pos = atomicAdd(&cursor[d], 1);
                if (pos < DEG_CAP) csr[d * DEG_CAP + pos] = src[i];
            }
        }
    } else {
        int idx = (blockIdx.x - scatterBlks) * blockDim.x + threadIdx.x;
        int wtot = (L + 1) * 4096;
        if (idx < wtot) {
            int layer = idx >> 12;
            int rem = idx & 4095;
            int k = rem >> 5;
            int n = (rem & 31) * 4;
            const float* w = (layer == 0) ? W0 : (Ws + (size_t)(layer - 1) * HID * HID);
            float4 v = *reinterpret_cast<const float4*>(w + (size_t)k * HID + n);
            int half = n >> 6;
            store_hilo64(wh, wl, (size_t)layer * 32768 + (size_t)half * 16384,
                         (uint32_t)k, (uint32_t)(n & 63), v);
        } else {
            int t = idx - wtot;
            if (t < N * 32) {
                int r = t >> 5;
                int k = (t & 31) * 4;
                float4 v = *reinterpret_cast<const float4*>(feat + (size_t)r * HID + k);
                store_hilo(xh, xl, (size_t)(r >> 6) * 16384, (uint32_t)(r & 63),
                           (uint32_t)k, v);
            }
        }
    }
    GDC_TRIGGER();
}

// ---------------------------------------------------------------------------
// Mean aggregation (at LTS floor; unchanged)
// ---------------------------------------------------------------------------
__global__ void agg_kernel(const unsigned char* __restrict__ hbase, int rowBytes,
                           const int* __restrict__ deg,
                           const int* __restrict__ csr,
                           unsigned char* __restrict__ xh,
                           unsigned char* __restrict__ xl, int N) {
    int node = (blockIdx.x * blockDim.x + threadIdx.x) >> 5;
    int lane = threadIdx.x & 31;
    if (node >= N) { GDC_WAIT(); GDC_TRIGGER(); return; }
    int d = deg[node];
    if (d > DEG_CAP) d = DEG_CAP;
    const int4* list4 = reinterpret_cast<const int4*>(csr + (size_t)node * DEG_CAP);
    GDC_WAIT();
    const unsigned char* hb = hbase + (uint32_t)(lane * 16);

    unsigned long long a0 = 0ull, a1 = 0ull, b0 = 0ull, b1 = 0ull;
    int i = 0;
    for (; i + 8 <= d; i += 8) {
        int4 l0 = list4[i >> 2];
        int4 l1 = list4[(i >> 2) + 1];
        ulonglong2 v0 = *reinterpret_cast<const ulonglong2*>(hb + (uint32_t)l0.x * rowBytes);
        ulonglong2 v1 = *reinterpret_cast<const ulonglong2*>(hb + (uint32_t)l0.y * rowBytes);
        ulonglong2 v2 = *reinterpret_cast<const ulonglong2*>(hb + (uint32_t)l0.z * rowBytes);
        ulonglong2 v3 = *reinterpret_cast<const ulonglong2*>(hb + (uint32_t)l0.w * rowBytes);
        ulonglong2 v4 = *reinterpret_cast<const ulonglong2*>(hb + (uint32_t)l1.x * rowBytes);
        ulonglong2 v5 = *reinterpret_cast<const ulonglong2*>(hb + (uint32_t)l1.y * rowBytes);
        ulonglong2 v6 = *reinterpret_cast<const ulonglong2*>(hb + (uint32_t)l1.z * rowBytes);
        ulonglong2 v7 = *reinterpret_cast<const ulonglong2*>(hb + (uint32_t)l1.w * rowBytes);
        add2(a0, v0.x); add2(a1, v0.y);
        add2(b0, v1.x); add2(b1, v1.y);
        add2(a0, v2.x); add2(a1, v2.y);
        add2(b0, v3.x); add2(b1, v3.y);
        add2(a0, v4.x); add2(a1, v4.y);
        add2(b0, v5.x); add2(b1, v5.y);
        add2(a0, v6.x); add2(a1, v6.y);
        add2(b0, v7.x); add2(b1, v7.y);
    }
    const int* list = csr + (size_t)node * DEG_CAP;
    for (; i < d; i++) {
        int sv = list[i];
        ulonglong2 v = *reinterpret_cast<const ulonglong2*>(hb + (uint32_t)sv * rowBytes);
        add2(a0, v.x); add2(a1, v.y);
    }
    add2(a0, b0); add2(a1, b1);

    float2 s01 = unpack2(a0);
    float2 s23 = unpack2(a1);
    float inv = (d > 0) ? (1.f / (float)d) : 0.f;
    float4 acc = make_float4(s01.x * inv, s01.y * inv, s23.x * inv, s23.y * inv);
    store_hilo(xh, xl, (size_t)(node >> 6) * 16384, (uint32_t)(node & 63),
               (uint32_t)(lane * 4), acc);
    GDC_TRIGGER();
}

// ---------------------------------------------------------------------------
// mma.sync GEMM + ReLU: 64x64 output per CTA (tile = b>>1, N-half = b&1).
// smem 64KB -> 3 CTAs/SM. cp.async prologue; W half in flight pre-wait.
// ---------------------------------------------------------------------------
#define GT 256
#define S_XH 0
#define S_XL 16384
#define S_BH 32768
#define S_BL 49152
#define GEMM_SMEM 65536

__global__ void __launch_bounds__(GT, 3)
gemm_mma_kernel(const unsigned char* __restrict__ xh,
                const unsigned char* __restrict__ xl,
                const unsigned char* __restrict__ wh,
                const unsigned char* __restrict__ wl,
                float* __restrict__ outBlk, int N, int outStride, int wFirst) {
    extern __shared__ char smem[];
    uint32_t sb = s2u(smem);
    int tid = threadIdx.x;
    int lane = tid & 31;
    int w = tid >> 5;
    int tile = blockIdx.x >> 1;
    int half = blockIdx.x & 1;
    int row0 = tile * 64;
    int col0 = half * 64;
    size_t xoff = (size_t)tile * 16384;
    size_t woff = (size_t)half * 16384;

    if (wFirst) {
        #pragma unroll
        for (int i = 0; i < 4; i++) {
            uint32_t o = (uint32_t)(tid + i * GT) * 16u;
            cp16(sb + S_BH + o, wh + woff + o);
            cp16(sb + S_BL + o, wl + woff + o);
        }
        CP_COMMIT();
        GDC_WAIT();
        #pragma unroll
        for (int i = 0; i < 4; i++) {
            uint32_t o = (uint32_t)(tid + i * GT) * 16u;
            cp16(sb + S_XH + o, xh + xoff + o);
            cp16(sb + S_XL + o, xl + xoff + o);
        }
        CP_COMMIT();
    } else {
        GDC_WAIT();
        #pragma unroll
        for (int i = 0; i < 4; i++) {
            uint32_t o = (uint32_t)(tid + i * GT) * 16u;
            cp16(sb + S_XH + o, xh + xoff + o);
            cp16(sb + S_XL + o, xl + xoff + o);
            cp16(sb + S_BH + o, wh + woff + o);
            cp16(sb + S_BL + o, wl + woff + o);
        }
        CP_COMMIT();
    }
    CP_WAIT0();
    __syncthreads();

    const int rw = (w & 3) * 16;    // 16-row group
    const int cw = (w >> 2) * 32;   // 32-col group within the 64-col half

    float acc[4][4];
    #pragma unroll
    for (int j = 0; j < 4; j++)
        #pragma unroll
        for (int q = 0; q < 4; q++) acc[j][q] = 0.f;

    #pragma unroll
    for (int kc = 0; kc < 8; kc++) {
        uint32_t ah[4], al[4];
        {
            uint32_t ar = (uint32_t)(rw + (lane & 15));
            uint32_t ak = (uint32_t)(kc * 16 + (lane >> 4) * 8);
            uint32_t so = swz(ar, ak);
            ldsm_x4(ah, sb + S_XH + so);
            ldsm_x4(al, sb + S_XL + so);
        }
        uint32_t bk = (uint32_t)(kc * 16 + (lane & 7) + ((lane >> 3) & 1) * 8);
        #pragma unroll
        for (int jj = 0; jj < 2; jj++) {
            uint32_t bn = (uint32_t)(cw + (lane >> 4) * 8 + jj * 16);
            uint32_t so = swz64(bk, bn);
            uint32_t bh4[4], bl4[4];
            ldsm_x4t(bh4, sb + S_BH + so);
            ldsm_x4t(bl4, sb + S_BL + so);
            #pragma unroll
            for (int h = 0; h < 2; h++) {
                int j = jj * 2 + h;
                const uint32_t* bh = bh4 + h * 2;
                const uint32_t* bl = bl4 + h * 2;
                mma_bf16(acc[j], ah, bh);
                mma_bf16(acc[j], al, bh);
                mma_bf16(acc[j], ah, bl);
            }
        }
    }

    int rA = row0 + rw + (lane >> 2);
    int rB = rA + 8;
    #pragma unroll
    for (int j = 0; j < 4; j++) {
        int c = col0 + cw + j * 8 + (lane & 3) * 2;
        if (rA < N) {
            float2 v = make_float2(fmaxf(acc[j][0], 0.f), fmaxf(acc[j][1], 0.f));
            *reinterpret_cast<float2*>(outBlk + (size_t)rA * outStride + c) = v;
        }
        if (rB < N) {
            float2 v = make_float2(fmaxf(acc[j][2], 0.f), fmaxf(acc[j][3], 0.f));
            *reinterpret_cast<float2*>(outBlk + (size_t)rB * outStride + c) = v;
        }
    }
    GDC_TRIGGER();
}

// ---------------------------------------------------------------------------
// launch: single stream; PDL attributes on the dependent chain
// ---------------------------------------------------------------------------
static void launch_pdl(void* fn, dim3 grid, dim3 block, size_t smem,
                       void** args) {
    cudaLaunchConfig_t cfg = {};
    cfg.gridDim = grid;
    cfg.blockDim = block;
    cfg.dynamicSmemBytes = smem;
    cfg.stream = 0;
    cudaLaunchAttribute attr[1];
    attr[0].id = cudaLaunchAttributeProgrammaticStreamSerialization;
    attr[0].val.programmaticStreamSerializationAllowed = 1;
    cfg.attrs = attr;
    cfg.numAttrs = 1;
    cudaLaunchKernelExC(&cfg, fn, args);
}

extern "C" void kernel_launch(void* const* d_in, const int* in_sizes, int n_in,
                              void* d_out, int out_size) {
    const float* feat = (const float*)d_in[0];
    const int*   src  = (const int*)d_in[1];
    const int*   dst  = (const int*)d_in[2];
    const float* W0   = (const float*)d_in[3];
    const float* Ws   = (const float*)d_in[4];
    float* out = (float*)d_out;

    int N = in_sizes[0] / HID;
    int E = in_sizes[1];
    int L = in_sizes[4] / (HID * HID);
    int outStride = (L + 1) * HID;
    int rowBytes = outStride * 4;

    int* counts;    cudaGetSymbolAddress((void**)&counts, g_counts);
    int* csr;       cudaGetSymbolAddress((void**)&csr, g_csr_src);
    unsigned char *xh, *xl, *wh, *wl;
    cudaGetSymbolAddress((void**)&xh, g_xh);
    cudaGetSymbolAddress((void**)&xl, g_xl);
    cudaGetSymbolAddress((void**)&wh, g_wh);
    cudaGetSymbolAddress((void**)&wl, g_wl);

    cudaFuncSetAttribute(gemm_mma_kernel, cudaFuncAttributeMaxDynamicSharedMemorySize,
                         GEMM_SMEM);

    int gemm_grid = ((N + 63) / 64) * 2;
    int eThreads4 = (E + 3) / 4;
    int scatterBlks = (eThreads4 + 255) / 256;
    int convBlks = ((L + 1) * 4096 + N * 32 + 255) / 256;

    cudaMemsetAsync(counts, 0, (size_t)N * sizeof(int), 0);
    prep_kernel<<<scatterBlks + convBlks, 256>>>(src, dst, counts, csr, E,
                                                 feat, W0, Ws, xh, xl, wh, wl,
                                                 L, N, scatterBlks);

    {
        int wFirst = 0;
        void* args[] = {&xh, &xl, &wh, &wl, &out, &N, &outStride, &wFirst};
        launch_pdl((void*)gemm_mma_kernel, dim3(gemm_grid), dim3(GT), GEMM_SMEM, args);
    }

    int agg_grid = (N + 7) / 8;
    for (int l = 0; l < L; l++) {
        const unsigned char* hb = reinterpret_cast<const unsigned char*>(out + (size_t)l * HID);
        void* aargs[] = {&hb, &rowBytes, &counts, &csr, &xh, &xl, &N};
        launch_pdl((void*)agg_kernel, dim3(agg_grid), dim3(256), 0, aargs);

        unsigned char* whl = wh + (size_t)(l + 1) * 32768;
        unsigned char* wll = wl + (size_t)(l + 1) * 32768;
        float* ob = out + (size_t)(l + 1) * HID;
        int wFirst = 1;
        void* gargs[] = {&xh, &xl, &whl, &wll, &ob, &N, &outStride, &wFirst};
        launch_pdl((void*)gemm_mma_kernel, dim3(gemm_grid), dim3(GT), GEMM_SMEM, gargs);
    }
    (void)n_in; (void)out_size;
}

// round 16
// speedup vs baseline: 1.0350x; 1.0350x over previous
#include <cuda_runtime.h>
#include <cuda_bf16.h>
#include <cstdint>

// ---------------------------------------------------------------------------
// ACCGraphSAGE: h0 = relu(feat@W0); 3x { agg = mean_in(h); h = relu(agg@Ws[l]) }
// out = concat([h0..h3], dim=1) -> [N, 512] fp32
// R16: critical-path attack. feat conversion moved into feat_gemm_kernel's
//      prologue BEFORE its PDL wait (runs concurrent with prep); prep now
//      only scatter (8 edges/thread) + W conversion. GEMM = R14 config.
// ---------------------------------------------------------------------------

#define MAX_N 50000
#define MAX_E 800000
#define HID 128
#define NTILES ((MAX_N + 63) / 64)
#define DEG_CAP 128

__device__ int g_counts[MAX_N];
__device__ int g_csr_src[MAX_N * DEG_CAP];
__device__ __align__(16) unsigned char g_xh[NTILES * 16384];
__device__ __align__(16) unsigned char g_xl[NTILES * 16384];
__device__ __align__(16) unsigned char g_wh[4 * 32768];
__device__ __align__(16) unsigned char g_wl[4 * 32768];

// ---------------------------------------------------------------------------
// helpers
// ---------------------------------------------------------------------------
#define GDC_WAIT()    asm volatile("griddepcontrol.wait;" ::: "memory")
#define GDC_TRIGGER() asm volatile("griddepcontrol.launch_dependents;" ::: "memory")
#define CP_COMMIT()   asm volatile("cp.async.commit_group;" ::: "memory")
#define CP_WAIT0()    asm volatile("cp.async.wait_group 0;" ::: "memory")

__device__ __forceinline__ void cp16(uint32_t saddr, const void* gaddr) {
    asm volatile("cp.async.cg.shared.global [%0], [%1], 16;"
                 :: "r"(saddr), "l"(gaddr) : "memory");
}

__device__ __forceinline__ uint32_t s2u(const void* p) {
    uint32_t a;
    asm("{ .reg .u64 t; cvta.to.shared.u64 t, %1; cvt.u32.u64 %0, t; }"
        : "=r"(a) : "l"(p));
    return a;
}

__device__ __forceinline__ uint32_t swz(uint32_t row, uint32_t kelem) {
    return row * 256u + ((((kelem >> 3) ^ (row & 7u)) & 15u) << 4) +
           ((kelem & 7u) << 1);
}

__device__ __forceinline__ void ldsm_x4(uint32_t* d, uint32_t addr) {
    asm volatile("ldmatrix.sync.aligned.m8n8.x4.shared.b16 {%0,%1,%2,%3}, [%4];"
                 : "=r"(d[0]), "=r"(d[1]), "=r"(d[2]), "=r"(d[3]) : "r"(addr));
}
__device__ __forceinline__ void ldsm_x4t(uint32_t* d, uint32_t addr) {
    asm volatile("ldmatrix.sync.aligned.m8n8.x4.trans.shared.b16 {%0,%1,%2,%3}, [%4];"
                 : "=r"(d[0]), "=r"(d[1]), "=r"(d[2]), "=r"(d[3]) : "r"(addr));
}
__device__ __forceinline__ void mma_bf16(float* c, const uint32_t* a,
                                         const uint32_t* b) {
    asm volatile(
        "mma.sync.aligned.m16n8k16.row.col.f32.bf16.bf16.f32 "
        "{%0,%1,%2,%3}, {%4,%5,%6,%7}, {%8,%9}, {%0,%1,%2,%3};"
        : "+f"(c[0]), "+f"(c[1]), "+f"(c[2]), "+f"(c[3])
        : "r"(a[0]), "r"(a[1]), "r"(a[2]), "r"(a[3]), "r"(b[0]), "r"(b[1]));
}

__device__ __forceinline__ void add2(unsigned long long& d, unsigned long long v) {
    asm("add.rn.f32x2 %0, %0, %1;" : "+l"(d) : "l"(v));
}
__device__ __forceinline__ float2 unpack2(unsigned long long v) {
    float2 f;
    asm("mov.b64 {%0, %1}, %2;" : "=f"(f.x), "=f"(f.y) : "l"(v));
    return f;
}

__device__ __forceinline__ void store_hilo(unsigned char* xh, unsigned char* xl,
                                           size_t tileBase, uint32_t r, uint32_t k,
                                           float4 v) {
    __nv_bfloat162 h01 = __floats2bfloat162_rn(v.x, v.y);
    __nv_bfloat162 h23 = __floats2bfloat162_rn(v.z, v.w);
    __nv_bfloat162 l01 = __floats2bfloat162_rn(v.x - __bfloat162float(h01.x),
                                               v.y - __bfloat162float(h01.y));
    __nv_bfloat162 l23 = __floats2bfloat162_rn(v.z - __bfloat162float(h23.x),
                                               v.w - __bfloat162float(h23.y));
    uint32_t o0 = swz(r, k), o1 = swz(r, k + 2);
    *reinterpret_cast<__nv_bfloat162*>(xh + tileBase + o0) = h01;
    *reinterpret_cast<__nv_bfloat162*>(xh + tileBase + o1) = h23;
    *reinterpret_cast<__nv_bfloat162*>(xl + tileBase + o0) = l01;
    *reinterpret_cast<__nv_bfloat162*>(xl + tileBase + o1) = l23;
}

// ---------------------------------------------------------------------------
// prep: scatter (8 edges/thread, bucketed CSR) + W conversion only.
// ---------------------------------------------------------------------------
__global__ void prep_kernel(const int* __restrict__ src, const int* __restrict__ dst,
                            int* __restrict__ cursor, int* __restrict__ csr, int E,
                            const float* __restrict__ W0,
                            const float* __restrict__ Ws,
                            unsigned char* __restrict__ wh,
                            unsigned char* __restrict__ wl,
                            int L, int scatterBlks) {
    if ((int)blockIdx.x < scatterBlks) {
        int i = (blockIdx.x * blockDim.x + threadIdx.x) * 8;
        if (i + 8 <= E) {
            int4 d0 = *reinterpret_cast<const int4*>(dst + i);
            int4 d1 = *reinterpret_cast<const int4*>(dst + i + 4);
            int4 s0 = *reinterpret_cast<const int4*>(src + i);
            int4 s1 = *reinterpret_cast<const int4*>(src + i + 4);
            int p0 = atomicAdd(&cursor[d0.x], 1);
            int p1 = atomicAdd(&cursor[d0.y], 1);
            int p2 = atomicAdd(&cursor[d0.z], 1);
            int p3 = atomicAdd(&cursor[d0.w], 1);
            int p4 = atomicAdd(&cursor[d1.x], 1);
            int p5 = atomicAdd(&cursor[d1.y], 1);
            int p6 = atomicAdd(&cursor[d1.z], 1);
            int p7 = atomicAdd(&cursor[d1.w], 1);
            if (p0 < DEG_CAP) csr[d0.x * DEG_CAP + p0] = s0.x;
            if (p1 < DEG_CAP) csr[d0.y * DEG_CAP + p1] = s0.y;
            if (p2 < DEG_CAP) csr[d0.z * DEG_CAP + p2] = s0.z;
            if (p3 < DEG_CAP) csr[d0.w * DEG_CAP + p3] = s0.w;
            if (p4 < DEG_CAP) csr[d1.x * DEG_CAP + p4] = s1.x;
            if (p5 < DEG_CAP) csr[d1.y * DEG_CAP + p5] = s1.y;
            if (p6 < DEG_CAP) csr[d1.z * DEG_CAP + p6] = s1.z;
            if (p7 < DEG_CAP) csr[d1.w * DEG_CAP + p7] = s1.w;
        } else {
            for (; i < E; i++) {
                int d = dst[i];
                int pos = atomicAdd(&cursor[d], 1);
                if (pos < DEG_CAP) csr[d * DEG_CAP + pos] = src[i];
            }
        }
    } else {
        int idx = (blockIdx.x - scatterBlks) * blockDim.x + threadIdx.x;
        if (idx < (L + 1) * 4096) {
            int layer = idx >> 12;
            int rem = idx & 4095;
            int k = rem >> 5;
            int n = (rem & 31) * 4;
            const float* w = (layer == 0) ? W0 : (Ws + (size_t)(layer - 1) * HID * HID);
            float4 v = *reinterpret_cast<const float4*>(w + (size_t)k * HID + n);
            store_hilo(wh, wl, (size_t)layer * 32768, (uint32_t)k, (uint32_t)n, v);
        }
    }
    GDC_TRIGGER();
}

// ---------------------------------------------------------------------------
// Mean aggregation (at LTS floor; unchanged)
// ---------------------------------------------------------------------------
__global__ void agg_kernel(const unsigned char* __restrict__ hbase, int rowBytes,
                           const int* __restrict__ deg,
                           const int* __restrict__ csr,
                           unsigned char* __restrict__ xh,
                           unsigned char* __restrict__ xl, int N) {
    int node = (blockIdx.x * blockDim.x + threadIdx.x) >> 5;
    int lane = threadIdx.x & 31;
    if (node >= N) { GDC_WAIT(); GDC_TRIGGER(); return; }
    int d = deg[node];
    if (d > DEG_CAP) d = DEG_CAP;
    const int4* list4 = reinterpret_cast<const int4*>(csr + (size_t)node * DEG_CAP);
    GDC_WAIT();
    const unsigned char* hb = hbase + (uint32_t)(lane * 16);

    unsigned long long a0 = 0ull, a1 = 0ull, b0 = 0ull, b1 = 0ull;
    int i = 0;
    for (; i + 8 <= d; i += 8) {
        int4 l0 = list4[i >> 2];
        int4 l1 = list4[(i >> 2) + 1];
        ulonglong2 v0 = *reinterpret_cast<const ulonglong2*>(hb + (uint32_t)l0.x * rowBytes);
        ulonglong2 v1 = *reinterpret_cast<const ulonglong2*>(hb + (uint32_t)l0.y * rowBytes);
        ulonglong2 v2 = *reinterpret_cast<const ulonglong2*>(hb + (uint32_t)l0.z * rowBytes);
        ulonglong2 v3 = *reinterpret_cast<const ulonglong2*>(hb + (uint32_t)l0.w * rowBytes);
        ulonglong2 v4 = *reinterpret_cast<const ulonglong2*>(hb + (uint32_t)l1.x * rowBytes);
        ulonglong2 v5 = *reinterpret_cast<const ulonglong2*>(hb + (uint32_t)l1.y * rowBytes);
        ulonglong2 v6 = *reinterpret_cast<const ulonglong2*>(hb + (uint32_t)l1.z * rowBytes);
        ulonglong2 v7 = *reinterpret_cast<const ulonglong2*>(hb + (uint32_t)l1.w * rowBytes);
        add2(a0, v0.x); add2(a1, v0.y);
        add2(b0, v1.x); add2(b1, v1.y);
        add2(a0, v2.x); add2(a1, v2.y);
        add2(b0, v3.x); add2(b1, v3.y);
        add2(a0, v4.x); add2(a1, v4.y);
        add2(b0, v5.x); add2(b1, v5.y);
        add2(a0, v6.x); add2(a1, v6.y);
        add2(b0, v7.x); add2(b1, v7.y);
    }
    const int* list = csr + (size_t)node * DEG_CAP;
    for (; i < d; i++) {
        int sv = list[i];
        ulonglong2 v = *reinterpret_cast<const ulonglong2*>(hb + (uint32_t)sv * rowBytes);
        add2(a0, v.x); add2(a1, v.y);
    }
    add2(a0, b0); add2(a1, b1);

    float2 s01 = unpack2(a0);
    float2 s23 = unpack2(a1);
    float inv = (d > 0) ? (1.f / (float)d) : 0.f;
    float4 acc = make_float4(s01.x * inv, s01.y * inv, s23.x * inv, s23.y * inv);
    store_hilo(xh, xl, (size_t)(node >> 6) * 16384, (uint32_t)(node & 63),
               (uint32_t)(lane * 4), acc);
    GDC_TRIGGER();
}

// ---------------------------------------------------------------------------
// shared mma mainloop + epilogue (R14 config: 64x128 tile, x4.trans B loads)
// ---------------------------------------------------------------------------
#define GT 256
#define S_XH 0
#define S_XL 16384
#define S_BH 32768
#define S_BL 65536
#define GEMM_SMEM 98304

__device__ __forceinline__ void mma_core(uint32_t sb, int tid, int row0,
                                         float* __restrict__ outBlk,
                                         int N, int outStride) {
    int lane = tid & 31;
    int w = tid >> 5;
    const int rw = (w & 1) * 32;
    const int cw = (w >> 1) * 32;

    float acc[2][4][4];
    #pragma unroll
    for (int i = 0; i < 2; i++)
        #pragma unroll
        for (int j = 0; j < 4; j++)
            #pragma unroll
            for (int q = 0; q < 4; q++) acc[i][j][q] = 0.f;

    #pragma unroll
    for (int kc = 0; kc < 8; kc++) {
        uint32_t ah[2][4], al[2][4];
        #pragma unroll
        for (int i = 0; i < 2; i++) {
            uint32_t ar = (uint32_t)(rw + i * 16 + (lane & 15));
            uint32_t ak = (uint32_t)(kc * 16 + (lane >> 4) * 8);
            uint32_t so = swz(ar, ak);
            ldsm_x4(ah[i], sb + S_XH + so);
            ldsm_x4(al[i], sb + S_XL + so);
        }
        uint32_t bk = (uint32_t)(kc * 16 + (lane & 7) + ((lane >> 3) & 1) * 8);
        #pragma unroll
        for (int jj = 0; jj < 2; jj++) {
            uint32_t bn = (uint32_t)(cw + (lane >> 4) * 8 + jj * 16);
            uint32_t so = swz(bk, bn);
            uint32_t bh4[4], bl4[4];
            ldsm_x4t(bh4, sb + S_BH + so);
            ldsm_x4t(bl4, sb + S_BL + so);
            #pragma unroll
            for (int h = 0; h < 2; h++) {
                int j = jj * 2 + h;
                const uint32_t* bh = bh4 + h * 2;
                const uint32_t* bl = bl4 + h * 2;
                mma_bf16(acc[0][j], ah[0], bh);
                mma_bf16(acc[1][j], ah[1], bh);
                mma_bf16(acc[0][j], al[0], bh);
                mma_bf16(acc[1][j], al[1], bh);
                mma_bf16(acc[0][j], ah[0], bl);
                mma_bf16(acc[1][j], ah[1], bl);
            }
        }
    }

    #pragma unroll
    for (int i = 0; i < 2; i++) {
        int rA = row0 + rw + i * 16 + (lane >> 2);
        int rB = rA + 8;
        #pragma unroll
        for (int j = 0; j < 4; j++) {
            int c = cw + j * 8 + (lane & 3) * 2;
            if (rA < N) {
                float2 v = make_float2(fmaxf(acc[i][j][0], 0.f),
                                       fmaxf(acc[i][j][1], 0.f));
                *reinterpret_cast<float2*>(outBlk + (size_t)rA * outStride + c) = v;
            }
            if (rB < N) {
                float2 v = make_float2(fmaxf(acc[i][j][2], 0.f),
                                       fmaxf(acc[i][j][3], 0.f));
                *reinterpret_cast<float2*>(outBlk + (size_t)rB * outStride + c) = v;
            }
        }
    }
}

// layer-0: fp32 feat -> smem hi/lo conversion BEFORE the PDL wait (feat is a
// harness input, independent of prep); after wait, only W cp.async.
__global__ void __launch_bounds__(GT, 2)
feat_gemm_kernel(const float* __restrict__ feat,
                 const unsigned char* __restrict__ wh,
                 const unsigned char* __restrict__ wl,
                 float* __restrict__ outBlk, int N, int outStride) {
    extern __shared__ char smem[];
    uint32_t sb = s2u(smem);
    int tid = threadIdx.x;
    int row0 = blockIdx.x * 64;

    // feat conversion (pre-wait; overlaps prep)
    unsigned char* sxh = reinterpret_cast<unsigned char*>(smem + S_XH);
    unsigned char* sxl = reinterpret_cast<unsigned char*>(smem + S_XL);
    #pragma unroll
    for (int i = 0; i < 8; i++) {
        int idx = tid + i * GT;          // 0..2047
        int r = idx >> 5;
        int k = (idx & 31) * 4;
        float4 v = make_float4(0.f, 0.f, 0.f, 0.f);
        int gr = row0 + r;
        if (gr < N) v = *reinterpret_cast<const float4*>(feat + (size_t)gr * HID + k);
        store_hilo(sxh, sxl, 0, (uint32_t)r, (uint32_t)k, v);
    }

    GDC_WAIT();
    #pragma unroll
    for (int i = 0; i < 8; i++) {
        uint32_t o = (uint32_t)(tid + i * GT) * 16u;
        cp16(sb + S_BH + o, wh + o);
        cp16(sb + S_BL + o, wl + o);
    }
    CP_COMMIT();
    CP_WAIT0();
    __syncthreads();

    mma_core(sb, tid, row0, outBlk, N, outStride);
    GDC_TRIGGER();
}

// layers 1..L: X tiles from agg; W cp.async in flight BEFORE the wait.
__global__ void __launch_bounds__(GT, 2)
gemm_mma_kernel(const unsigned char* __restrict__ xh,
                const unsigned char* __restrict__ xl,
                const unsigned char* __restrict__ wh,
                const unsigned char* __restrict__ wl,
                float* __restrict__ outBlk, int N, int outStride) {
    extern __shared__ char smem[];
    uint32_t sb = s2u(smem);
    int tid = threadIdx.x;
    int row0 = blockIdx.x * 64;
    size_t xoff = (size_t)blockIdx.x * 16384;

    #pragma unroll
    for (int i = 0; i < 8; i++) {
        uint32_t o = (uint32_t)(tid + i * GT) * 16u;
        cp16(sb + S_BH + o, wh + o);
        cp16(sb + S_BL + o, wl + o);
    }
    CP_COMMIT();
    GDC_WAIT();
    #pragma unroll
    for (int i = 0; i < 4; i++) {
        uint32_t o = (uint32_t)(tid + i * GT) * 16u;
        cp16(sb + S_XH + o, xh + xoff + o);
        cp16(sb + S_XL + o, xl + xoff + o);
    }
    CP_COMMIT();
    CP_WAIT0();
    __syncthreads();

    mma_core(sb, tid, row0, outBlk, N, outStride);
    GDC_TRIGGER();
}

// ---------------------------------------------------------------------------
// launch: single stream; PDL attributes on the dependent chain
// ---------------------------------------------------------------------------
static void launch_pdl(void* fn, dim3 grid, dim3 block, size_t smem,
                       void** args) {
    cudaLaunchConfig_t cfg = {};
    cfg.gridDim = grid;
    cfg.blockDim = block;
    cfg.dynamicSmemBytes = smem;
    cfg.stream = 0;
    cudaLaunchAttribute attr[1];
    attr[0].id = cudaLaunchAttributeProgrammaticStreamSerialization;
    attr[0].val.programmaticStreamSerializationAllowed = 1;
    cfg.attrs = attr;
    cfg.numAttrs = 1;
    cudaLaunchKernelExC(&cfg, fn, args);
}

extern "C" void kernel_launch(void* const* d_in, const int* in_sizes, int n_in,
                              void* d_out, int out_size) {
    const float* feat = (const float*)d_in[0];
    const int*   src  = (const int*)d_in[1];
    const int*   dst  = (const int*)d_in[2];
    const float* W0   = (const float*)d_in[3];
    const float* Ws   = (const float*)d_in[4];
    float* out = (float*)d_out;

    int N = in_sizes[0] / HID;
    int E = in_sizes[1];
    int L = in_sizes[4] / (HID * HID);
    int outStride = (L + 1) * HID;
    int rowBytes = outStride * 4;

    int* counts;    cudaGetSymbolAddress((void**)&counts, g_counts);
    int* csr;       cudaGetSymbolAddress((void**)&csr, g_csr_src);
    unsigned char *xh, *xl, *wh, *wl;
    cudaGetSymbolAddress((void**)&xh, g_xh);
    cudaGetSymbolAddress((void**)&xl, g_xl);
    cudaGetSymbolAddress((void**)&wh, g_wh);
    cudaGetSymbolAddress((void**)&wl, g_wl);

    cudaFuncSetAttribute(feat_gemm_kernel, cudaFuncAttributeMaxDynamicSharedMemorySize,
                         GEMM_SMEM);
    cudaFuncSetAttribute(gemm_mma_kernel, cudaFuncAttributeMaxDynamicSharedMemorySize,
                         GEMM_SMEM);

    int gemm_grid = (N + 63) / 64;
    int eThreads8 = (E + 7) / 8;
    int scatterBlks = (eThreads8 + 255) / 256;
    int wconvBlks = ((L + 1) * 4096 + 255) / 256;

    cudaMemsetAsync(counts, 0, (size_t)N * sizeof(int), 0);
    prep_kernel<<<scatterBlks + wconvBlks, 256>>>(src, dst, counts, csr, E,
                                                  W0, Ws, wh, wl, L, scatterBlks);

    // layer-0 GEMM: feat conversion pre-wait, W after (depends on prep)
    {
        void* args[] = {&feat, &wh, &wl, &out, &N, &outStride};
        launch_pdl((void*)feat_gemm_kernel, dim3(gemm_grid), dim3(GT), GEMM_SMEM, args);
    }

    int agg_grid = (N + 7) / 8;
    for (int l = 0; l < L; l++) {
        const unsigned char* hb = reinterpret_cast<const unsigned char*>(out + (size_t)l * HID);
        void* aargs[] = {&hb, &rowBytes, &counts, &csr, &xh, &xl, &N};
        launch_pdl((void*)agg_kernel, dim3(agg_grid), dim3(256), 0, aargs);

        unsigned char* whl = wh + (size_t)(l + 1) * 32768;
        unsigned char* wll = wl + (size_t)(l + 1) * 32768;
        float* ob = out + (size_t)(l + 1) * HID;
        void* gargs[] = {&xh, &xl, &whl, &wll, &ob, &N, &outStride};
        launch_pdl((void*)gemm_mma_kernel, dim3(gemm_grid), dim3(GT), GEMM_SMEM, gargs);
    }
    (void)n_in; (void)out_size;
}

// round 17
// speedup vs baseline: 1.1172x; 1.0794x over previous
#include <cuda_runtime.h>
#include <cuda_bf16.h>
#include <cuda_fp16.h>
#include <cstdint>

// ---------------------------------------------------------------------------
// ACCGraphSAGE: h0 = relu(feat@W0); 3x { agg = mean_in(h); h = relu(agg@Ws[l]) }
// out = concat([h0..h3], dim=1) -> [N, 512] fp32
// R17: fp16 gather mirror. GEMM epilogues also write h as fp16 into g_hf;
//      agg gathers 256B/row (half2) instead of 512B fp32 -> agg traffic
//      halved. Accumulation fp32; hi/lo bf16 GEMM path unchanged; out fp32.
// ---------------------------------------------------------------------------

#define MAX_N 50000
#define MAX_E 800000
#define HID 128
#define NTILES ((MAX_N + 63) / 64)
#define DEG_CAP 128

__device__ int g_counts[MAX_N];
__device__ int g_csr_src[MAX_N * DEG_CAP];
__device__ __align__(16) unsigned char g_xh[NTILES * 16384];
__device__ __align__(16) unsigned char g_xl[NTILES * 16384];
__device__ __align__(16) unsigned char g_wh[4 * 32768];
__device__ __align__(16) unsigned char g_wl[4 * 32768];
__device__ __align__(16) __half g_hf[MAX_N * HID];   // fp16 mirror of current h

// ---------------------------------------------------------------------------
// helpers
// ---------------------------------------------------------------------------
#define GDC_WAIT()    asm volatile("griddepcontrol.wait;" ::: "memory")
#define GDC_TRIGGER() asm volatile("griddepcontrol.launch_dependents;" ::: "memory")
#define CP_COMMIT()   asm volatile("cp.async.commit_group;" ::: "memory")
#define CP_WAIT0()    asm volatile("cp.async.wait_group 0;" ::: "memory")

__device__ __forceinline__ void cp16(uint32_t saddr, const void* gaddr) {
    asm volatile("cp.async.cg.shared.global [%0], [%1], 16;"
                 :: "r"(saddr), "l"(gaddr) : "memory");
}

__device__ __forceinline__ uint32_t s2u(const void* p) {
    uint32_t a;
    asm("{ .reg .u64 t; cvta.to.shared.u64 t, %1; cvt.u32.u64 %0, t; }"
        : "=r"(a) : "l"(p));
    return a;
}

__device__ __forceinline__ uint32_t swz(uint32_t row, uint32_t kelem) {
    return row * 256u + ((((kelem >> 3) ^ (row & 7u)) & 15u) << 4) +
           ((kelem & 7u) << 1);
}

__device__ __forceinline__ void ldsm_x4(uint32_t* d, uint32_t addr) {
    asm volatile("ldmatrix.sync.aligned.m8n8.x4.shared.b16 {%0,%1,%2,%3}, [%4];"
                 : "=r"(d[0]), "=r"(d[1]), "=r"(d[2]), "=r"(d[3]) : "r"(addr));
}
__device__ __forceinline__ void ldsm_x4t(uint32_t* d, uint32_t addr) {
    asm volatile("ldmatrix.sync.aligned.m8n8.x4.trans.shared.b16 {%0,%1,%2,%3}, [%4];"
                 : "=r"(d[0]), "=r"(d[1]), "=r"(d[2]), "=r"(d[3]) : "r"(addr));
}
__device__ __forceinline__ void mma_bf16(float* c, const uint32_t* a,
                                         const uint32_t* b) {
    asm volatile(
        "mma.sync.aligned.m16n8k16.row.col.f32.bf16.bf16.f32 "
        "{%0,%1,%2,%3}, {%4,%5,%6,%7}, {%8,%9}, {%0,%1,%2,%3};"
        : "+f"(c[0]), "+f"(c[1]), "+f"(c[2]), "+f"(c[3])
        : "r"(a[0]), "r"(a[1]), "r"(a[2]), "r"(a[3]), "r"(b[0]), "r"(b[1]));
}

__device__ __forceinline__ void store_hilo(unsigned char* xh, unsigned char* xl,
                                           size_t tileBase, uint32_t r, uint32_t k,
                                           float4 v) {
    __nv_bfloat162 h01 = __floats2bfloat162_rn(v.x, v.y);
    __nv_bfloat162 h23 = __floats2bfloat162_rn(v.z, v.w);
    __nv_bfloat162 l01 = __floats2bfloat162_rn(v.x - __bfloat162float(h01.x),
                                               v.y - __bfloat162float(h01.y));
    __nv_bfloat162 l23 = __floats2bfloat162_rn(v.z - __bfloat162float(h23.x),
                                               v.w - __bfloat162float(h23.y));
    uint32_t o0 = swz(r, k), o1 = swz(r, k + 2);
    *reinterpret_cast<__nv_bfloat162*>(xh + tileBase + o0) = h01;
    *reinterpret_cast<__nv_bfloat162*>(xh + tileBase + o1) = h23;
    *reinterpret_cast<__nv_bfloat162*>(xl + tileBase + o0) = l01;
    *reinterpret_cast<__nv_bfloat162*>(xl + tileBase + o1) = l23;
}

// ---------------------------------------------------------------------------
// prep: scatter (8 edges/thread, bucketed CSR) + W conversion only.
// ---------------------------------------------------------------------------
__global__ void prep_kernel(const int* __restrict__ src, const int* __restrict__ dst,
                            int* __restrict__ cursor, int* __restrict__ csr, int E,
                            const float* __restrict__ W0,
                            const float* __restrict__ Ws,
                            unsigned char* __restrict__ wh,
                            unsigned char* __restrict__ wl,
                            int L, int scatterBlks) {
    if ((int)blockIdx.x < scatterBlks) {
        int i = (blockIdx.x * blockDim.x + threadIdx.x) * 8;
        if (i + 8 <= E) {
            int4 d0 = *reinterpret_cast<const int4*>(dst + i);
            int4 d1 = *reinterpret_cast<const int4*>(dst + i + 4);
            int4 s0 = *reinterpret_cast<const int4*>(src + i);
            int4 s1 = *reinterpret_cast<const int4*>(src + i + 4);
            int p0 = atomicAdd(&cursor[d0.x], 1);
            int p1 = atomicAdd(&cursor[d0.y], 1);
            int p2 = atomicAdd(&cursor[d0.z], 1);
            int p3 = atomicAdd(&cursor[d0.w], 1);
            int p4 = atomicAdd(&cursor[d1.x], 1);
            int p5 = atomicAdd(&cursor[d1.y], 1);
            int p6 = atomicAdd(&cursor[d1.z], 1);
            int p7 = atomicAdd(&cursor[d1.w], 1);
            if (p0 < DEG_CAP) csr[d0.x * DEG_CAP + p0] = s0.x;
            if (p1 < DEG_CAP) csr[d0.y * DEG_CAP + p1] = s0.y;
            if (p2 < DEG_CAP) csr[d0.z * DEG_CAP + p2] = s0.z;
            if (p3 < DEG_CAP) csr[d0.w * DEG_CAP + p3] = s0.w;
            if (p4 < DEG_CAP) csr[d1.x * DEG_CAP + p4] = s1.x;
            if (p5 < DEG_CAP) csr[d1.y * DEG_CAP + p5] = s1.y;
            if (p6 < DEG_CAP) csr[d1.z * DEG_CAP + p6] = s1.z;
            if (p7 < DEG_CAP) csr[d1.w * DEG_CAP + p7] = s1.w;
        } else {
            for (; i < E; i++) {
                int d = dst[i];
                int pos = atomicAdd(&cursor[d], 1);
                if (pos < DEG_CAP) csr[d * DEG_CAP + pos] = src[i];
            }
        }
    } else {
        int idx = (blockIdx.x - scatterBlks) * blockDim.x + threadIdx.x;
        if (idx < (L + 1) * 4096) {
            int layer = idx >> 12;
            int rem = idx & 4095;
            int k = rem >> 5;
            int n = (rem & 31) * 4;
            const float* w = (layer == 0) ? W0 : (Ws + (size_t)(layer - 1) * HID * HID);
            float4 v = *reinterpret_cast<const float4*>(w + (size_t)k * HID + n);
            store_hilo(wh, wl, (size_t)layer * 32768, (uint32_t)k, (uint32_t)n, v);
        }
    }
    GDC_TRIGGER();
}

// ---------------------------------------------------------------------------
// Mean aggregation over fp16 mirror rows (256B/row). fp32 accumulation.
// ---------------------------------------------------------------------------
__global__ void agg_kernel(const __half* __restrict__ hf,
                           const int* __restrict__ deg,
                           const int* __restrict__ csr,
                           unsigned char* __restrict__ xh,
                           unsigned char* __restrict__ xl, int N) {
    int node = (blockIdx.x * blockDim.x + threadIdx.x) >> 5;
    int lane = threadIdx.x & 31;
    if (node >= N) { GDC_WAIT(); GDC_TRIGGER(); return; }
    int d = deg[node];
    if (d > DEG_CAP) d = DEG_CAP;
    const int4* list4 = reinterpret_cast<const int4*>(csr + (size_t)node * DEG_CAP);
    GDC_WAIT();
    const unsigned char* hb = reinterpret_cast<const unsigned char*>(hf) + lane * 8;

    float4 acc = make_float4(0.f, 0.f, 0.f, 0.f);
    int i = 0;
    for (; i + 8 <= d; i += 8) {
        int4 l0 = list4[i >> 2];
        int4 l1 = list4[(i >> 2) + 1];
        uint2 u[8];
        u[0] = *reinterpret_cast<const uint2*>(hb + (uint32_t)l0.x * 256u);
        u[1] = *reinterpret_cast<const uint2*>(hb + (uint32_t)l0.y * 256u);
        u[2] = *reinterpret_cast<const uint2*>(hb + (uint32_t)l0.z * 256u);
        u[3] = *reinterpret_cast<const uint2*>(hb + (uint32_t)l0.w * 256u);
        u[4] = *reinterpret_cast<const uint2*>(hb + (uint32_t)l1.x * 256u);
        u[5] = *reinterpret_cast<const uint2*>(hb + (uint32_t)l1.y * 256u);
        u[6] = *reinterpret_cast<const uint2*>(hb + (uint32_t)l1.z * 256u);
        u[7] = *reinterpret_cast<const uint2*>(hb + (uint32_t)l1.w * 256u);
        #pragma unroll
        for (int q = 0; q < 8; q++) {
            float2 f0 = __half22float2(*reinterpret_cast<const __half2*>(&u[q].x));
            float2 f1 = __half22float2(*reinterpret_cast<const __half2*>(&u[q].y));
            acc.x += f0.x; acc.y += f0.y; acc.z += f1.x; acc.w += f1.y;
        }
    }
    const int* list = csr + (size_t)node * DEG_CAP;
    for (; i < d; i++) {
        uint2 u = *reinterpret_cast<const uint2*>(hb + (uint32_t)list[i] * 256u);
        float2 f0 = __half22float2(*reinterpret_cast<const __half2*>(&u.x));
        float2 f1 = __half22float2(*reinterpret_cast<const __half2*>(&u.y));
        acc.x += f0.x; acc.y += f0.y; acc.z += f1.x; acc.w += f1.y;
    }
    float inv = (d > 0) ? (1.f / (float)d) : 0.f;
    acc.x *= inv; acc.y *= inv; acc.z *= inv; acc.w *= inv;
    store_hilo(xh, xl, (size_t)(node >> 6) * 16384, (uint32_t)(node & 63),
               (uint32_t)(lane * 4), acc);
    GDC_TRIGGER();
}

// ---------------------------------------------------------------------------
// shared mma mainloop + epilogue (64x128 tile, x4.trans B loads).
// Epilogue writes fp32 to out and (optionally) fp16 to the mirror.
// ---------------------------------------------------------------------------
#define GT 256
#define S_XH 0
#define S_XL 16384
#define S_BH 32768
#define S_BL 65536
#define GEMM_SMEM 98304

__device__ __forceinline__ void mma_core(uint32_t sb, int tid, int row0,
                                         float* __restrict__ outBlk,
                                         __half* __restrict__ hf,
                                         int N, int outStride) {
    int lane = tid & 31;
    int w = tid >> 5;
    const int rw = (w & 1) * 32;
    const int cw = (w >> 1) * 32;

    float acc[2][4][4];
    #pragma unroll
    for (int i = 0; i < 2; i++)
        #pragma unroll
        for (int j = 0; j < 4; j++)
            #pragma unroll
            for (int q = 0; q < 4; q++) acc[i][j][q] = 0.f;

    #pragma unroll
    for (int kc = 0; kc < 8; kc++) {
        uint32_t ah[2][4], al[2][4];
        #pragma unroll
        for (int i = 0; i < 2; i++) {
            uint32_t ar = (uint32_t)(rw + i * 16 + (lane & 15));
            uint32_t ak = (uint32_t)(kc * 16 + (lane >> 4) * 8);
            uint32_t so = swz(ar, ak);
            ldsm_x4(ah[i], sb + S_XH + so);
            ldsm_x4(al[i], sb + S_XL + so);
        }
        uint32_t bk = (uint32_t)(kc * 16 + (lane & 7) + ((lane >> 3) & 1) * 8);
        #pragma unroll
        for (int jj = 0; jj < 2; jj++) {
            uint32_t bn = (uint32_t)(cw + (lane >> 4) * 8 + jj * 16);
            uint32_t so = swz(bk, bn);
            uint32_t bh4[4], bl4[4];
            ldsm_x4t(bh4, sb + S_BH + so);
            ldsm_x4t(bl4, sb + S_BL + so);
            #pragma unroll
            for (int h = 0; h < 2; h++) {
                int j = jj * 2 + h;
                const uint32_t* bh = bh4 + h * 2;
                const uint32_t* bl = bl4 + h * 2;
                mma_bf16(acc[0][j], ah[0], bh);
                mma_bf16(acc[1][j], ah[1], bh);
                mma_bf16(acc[0][j], al[0], bh);
                mma_bf16(acc[1][j], al[1], bh);
                mma_bf16(acc[0][j], ah[0], bl);
                mma_bf16(acc[1][j], ah[1], bl);
            }
        }
    }

    #pragma unroll
    for (int i = 0; i < 2; i++) {
        int rA = row0 + rw + i * 16 + (lane >> 2);
        int rB = rA + 8;
        #pragma unroll
        for (int j = 0; j < 4; j++) {
            int c = cw + j * 8 + (lane & 3) * 2;
            if (rA < N) {
                float2 v = make_float2(fmaxf(acc[i][j][0], 0.f),
                                       fmaxf(acc[i][j][1], 0.f));
                *reinterpret_cast<float2*>(outBlk + (size_t)rA * outStride + c) = v;
                if (hf)
                    *reinterpret_cast<__half2*>(hf + (size_t)rA * HID + c) =
                        __floats2half2_rn(v.x, v.y);
            }
            if (rB < N) {
                float2 v = make_float2(fmaxf(acc[i][j][2], 0.f),
                                       fmaxf(acc[i][j][3], 0.f));
                *reinterpret_cast<float2*>(outBlk + (size_t)rB * outStride + c) = v;
                if (hf)
                    *reinterpret_cast<__half2*>(hf + (size_t)rB * HID + c) =
                        __floats2half2_rn(v.x, v.y);
            }
        }
    }
}

// layer-0: fp32 feat -> smem hi/lo conversion BEFORE the PDL wait.
__global__ void __launch_bounds__(GT, 2)
feat_gemm_kernel(const float* __restrict__ feat,
                 const unsigned char* __restrict__ wh,
                 const unsigned char* __restrict__ wl,
                 float* __restrict__ outBlk, __half* __restrict__ hf,
                 int N, int outStride) {
    extern __shared__ char smem[];
    uint32_t sb = s2u(smem);
    int tid = threadIdx.x;
    int row0 = blockIdx.x * 64;

    unsigned char* sxh = reinterpret_cast<unsigned char*>(smem + S_XH);
    unsigned char* sxl = reinterpret_cast<unsigned char*>(smem + S_XL);
    #pragma unroll
    for (int i = 0; i < 8; i++) {
        int idx = tid + i * GT;
        int r = idx >> 5;
        int k = (idx & 31) * 4;
        float4 v = make_float4(0.f, 0.f, 0.f, 0.f);
        int gr = row0 + r;
        if (gr < N) v = *reinterpret_cast<const float4*>(feat + (size_t)gr * HID + k);
        store_hilo(sxh, sxl, 0, (uint32_t)r, (uint32_t)k, v);
    }

    GDC_WAIT();
    #pragma unroll
    for (int i = 0; i < 8; i++) {
        uint32_t o = (uint32_t)(tid + i * GT) * 16u;
        cp16(sb + S_BH + o, wh + o);
        cp16(sb + S_BL + o, wl + o);
    }
    CP_COMMIT();
    CP_WAIT0();
    __syncthreads();

    mma_core(sb, tid, row0, outBlk, hf, N, outStride);
    GDC_TRIGGER();
}

// layers 1..L: X tiles from agg; W cp.async in flight BEFORE the wait.
__global__ void __launch_bounds__(GT, 2)
gemm_mma_kernel(const unsigned char* __restrict__ xh,
                const unsigned char* __restrict__ xl,
                const unsigned char* __restrict__ wh,
                const unsigned char* __restrict__ wl,
                float* __restrict__ outBlk, __half* __restrict__ hf,
                int N, int outStride) {
    extern __shared__ char smem[];
    uint32_t sb = s2u(smem);
    int tid = threadIdx.x;
    int row0 = blockIdx.x * 64;
    size_t xoff = (size_t)blockIdx.x * 16384;

    #pragma unroll
    for (int i = 0; i < 8; i++) {
        uint32_t o = (uint32_t)(tid + i * GT) * 16u;
        cp16(sb + S_BH + o, wh + o);
        cp16(sb + S_BL + o, wl + o);
    }
    CP_COMMIT();
    GDC_WAIT();
    #pragma unroll
    for (int i = 0; i < 4; i++) {
        uint32_t o = (uint32_t)(tid + i * GT) * 16u;
        cp16(sb + S_XH + o, xh + xoff + o);
        cp16(sb + S_XL + o, xl + xoff + o);
    }
    CP_COMMIT();
    CP_WAIT0();
    __syncthreads();

    mma_core(sb, tid, row0, outBlk, hf, N, outStride);
    GDC_TRIGGER();
}

// ---------------------------------------------------------------------------
// launch: single stream; PDL attributes on the dependent chain
// ---------------------------------------------------------------------------
static void launch_pdl(void* fn, dim3 grid, dim3 block, size_t smem,
                       void** args) {
    cudaLaunchConfig_t cfg = {};
    cfg.gridDim = grid;
    cfg.blockDim = block;
    cfg.dynamicSmemBytes = smem;
    cfg.stream = 0;
    cudaLaunchAttribute attr[1];
    attr[0].id = cudaLaunchAttributeProgrammaticStreamSerialization;
    attr[0].val.programmaticStreamSerializationAllowed = 1;
    cfg.attrs = attr;
    cfg.numAttrs = 1;
    cudaLaunchKernelExC(&cfg, fn, args);
}

extern "C" void kernel_launch(void* const* d_in, const int* in_sizes, int n_in,
                              void* d_out, int out_size) {
    const float* feat = (const float*)d_in[0];
    const int*   src  = (const int*)d_in[1];
    const int*   dst  = (const int*)d_in[2];
    const float* W0   = (const float*)d_in[3];
    const float* Ws   = (const float*)d_in[4];
    float* out = (float*)d_out;

    int N = in_sizes[0] / HID;
    int E = in_sizes[1];
    int L = in_sizes[4] / (HID * HID);
    int outStride = (L + 1) * HID;

    int* counts;    cudaGetSymbolAddress((void**)&counts, g_counts);
    int* csr;       cudaGetSymbolAddress((void**)&csr, g_csr_src);
    unsigned char *xh, *xl, *wh, *wl;
    __half* hf;
    cudaGetSymbolAddress((void**)&xh, g_xh);
    cudaGetSymbolAddress((void**)&xl, g_xl);
    cudaGetSymbolAddress((void**)&wh, g_wh);
    cudaGetSymbolAddress((void**)&wl, g_wl);
    cudaGetSymbolAddress((void**)&hf, g_hf);

    cudaFuncSetAttribute(feat_gemm_kernel, cudaFuncAttributeMaxDynamicSharedMemorySize,
                         GEMM_SMEM);
    cudaFuncSetAttribute(gemm_mma_kernel, cudaFuncAttributeMaxDynamicSharedMemorySize,
                         GEMM_SMEM);

    int gemm_grid = (N + 63) / 64;
    int eThreads8 = (E + 7) / 8;
    int scatterBlks = (eThreads8 + 255) / 256;
    int wconvBlks = ((L + 1) * 4096 + 255) / 256;

    cudaMemsetAsync(counts, 0, (size_t)N * sizeof(int), 0);
    prep_kernel<<<scatterBlks + wconvBlks, 256>>>(src, dst, counts, csr, E,
                                                  W0, Ws, wh, wl, L, scatterBlks);

    // layer-0 GEMM: feat conversion pre-wait; writes fp32 out + fp16 mirror
    {
        void* args[] = {&feat, &wh, &wl, &out, &hf, &N, &outStride};
        launch_pdl((void*)feat_gemm_kernel, dim3(gemm_grid), dim3(GT), GEMM_SMEM, args);
    }

    int agg_grid = (N + 7) / 8;
    for (int l = 0; l < L; l++) {
        void* aargs[] = {&hf, &counts, &csr, &xh, &xl, &N};
        launch_pdl((void*)agg_kernel, dim3(agg_grid), dim3(256), 0, aargs);

        unsigned char* whl = wh + (size_t)(l + 1) * 32768;
        unsigned char* wll = wl + (size_t)(l + 1) * 32768;
        float* ob = out + (size_t)(l + 1) * HID;
        __half* hfl = (l + 1 < L) ? hf : (__half*)nullptr;  // last layer: no mirror
        void* gargs[] = {&xh, &xl, &whl, &wll, &ob, &hfl, &N, &outStride};
        launch_pdl((void*)gemm_mma_kernel, dim3(gemm_grid), dim3(GT), GEMM_SMEM, gargs);
    }
    (void)n_in; (void)out_size;
}